// round 10
// baseline (speedup 1.0000x reference)
#include <cuda_runtime.h>

// Problem constants (static per init_kwargs)
#define N_IMG 8
#define CIN   64
#define H     112
#define W     112
#define HW    (H * W)        // 12544 patches per image (stride 1, pad 1)
#define DPAT  576            // Cin * K * K
#define COUT  64
#define MEM   1025           // memo table size

// Tiling for the fused csum+bins kernel
#define TILE  16
#define HALO  18             // TILE + 2
#define NHALO (HALO * HALO)  // 324
#define TPI   7              // tiles per image dim (112/16)

// Scratch (device globals — no allocation allowed).
// g_first holds ENCODED first-patch: enc = HW - p (so 0 == "empty bin").
// Zero-initialized at module load; k_scatter re-zeros it each replay, so the
// graph is self-restoring with no dedicated init kernel.
__device__ int   g_bins[N_IMG * HW];
__device__ int   g_first[N_IMG * MEM];
__device__ float g_rep[N_IMG * MEM * COUT];

// ---------------------------------------------------------------------------
// Kernel 1 (fused): per-pixel 64-channel sum (double, 4 independent chains)
// into an 18x18 SMEM halo tile, then 3x3 box sum -> quantized summary -> bin.
// Final fp32 ops replicate the reference exactly:
//   mean = f32(sum) / 576.0f ; q = mean * 100.0f ; summ = trunc_to_int(q)
// First-occurrence via atomicMax on (HW - p) so empty == 0.
// ---------------------------------------------------------------------------
__global__ void k_fused(const float* __restrict__ fmap) {
    __shared__ double sh[NHALO];

    int blk = blockIdx.x;
    int n   = blk / (TPI * TPI);
    int t   = blk - n * (TPI * TPI);
    int ty  = t / TPI, tx = t - (t / TPI) * TPI;
    int gy0 = ty * TILE - 1;     // halo origin (can be -1)
    int gx0 = tx * TILE - 1;

    const float* fb = fmap + n * CIN * HW;

    // Phase 1: channel sums for halo pixels (OOB -> 0, matching zero-pad).
    for (int h = threadIdx.x; h < NHALO; h += blockDim.x) {
        int hy = h / HALO;
        int hx = h - hy * HALO;
        int gy = gy0 + hy;
        int gx = gx0 + hx;
        double s = 0.0;
        if ((unsigned)gy < H && (unsigned)gx < W) {
            const float* p = fb + gy * W + gx;
            double a0 = 0.0, a1 = 0.0, a2 = 0.0, a3 = 0.0;
#pragma unroll
            for (int c = 0; c < CIN; c += 4) {
                a0 += (double)__ldg(p + (c + 0) * HW);
                a1 += (double)__ldg(p + (c + 1) * HW);
                a2 += (double)__ldg(p + (c + 2) * HW);
                a3 += (double)__ldg(p + (c + 3) * HW);
            }
            s = (a0 + a1) + (a2 + a3);
        }
        sh[h] = s;
    }
    __syncthreads();

    // Phase 2: 3x3 box sum, quantize, bin, scatter first-occurrence.
    int ly = threadIdx.x / TILE;
    int lx = threadIdx.x - ly * TILE;
    int gy = ty * TILE + ly;
    int gx = tx * TILE + lx;

    double s = 0.0;
#pragma unroll
    for (int dy = 0; dy < 3; ++dy)
#pragma unroll
        for (int dx = 0; dx < 3; ++dx)
            s += sh[(ly + dy) * HALO + (lx + dx)];

    float sf   = (float)s;
    float mean = __fdiv_rn(sf, 576.0f);      // IEEE division
    float q    = __fmul_rn(mean, 100.0f);
    int summ   = __float2int_rz(q);          // trunc toward zero == astype(int32)
    int bin    = summ + 512;                 // summ - MIN_SUMMARY
    bin = bin < 0 ? 0 : (bin > MEM - 1 ? MEM - 1 : bin);

    int p = gy * W + gx;
    g_bins[n * HW + p] = bin;
    atomicMax(&g_first[n * MEM + bin], HW - p);   // min-p == max-(HW-p)
}

// ---------------------------------------------------------------------------
// Kernel 2: representative GEMM rows. One 64-thread block per (image, bin).
// Inactive bins (enc==0) exit immediately (~400 of 8200 blocks do work).
// Thread t stages its channel's 3x3 window into SMEM (d = c*9 + kh*3 + kw,
// matching conv_general_dilated_patches order), then computes cout t.
// ---------------------------------------------------------------------------
__global__ void k_rep(const float* __restrict__ fmap,
                      const float* __restrict__ weight,
                      const float* __restrict__ bias) {
    int n = blockIdx.x / MEM;
    int b = blockIdx.x - n * MEM;
    int enc = g_first[n * MEM + b];
    if (enc <= 0) return;                    // empty bin
    int fp = HW - enc;                       // first patch index

    __shared__ float sp[DPAT];
    int t = threadIdx.x;                     // 0..63
    int y = fp / W;
    int x = fp - y * W;

    const float* fb = fmap + (n * CIN + t) * HW;
#pragma unroll
    for (int kh = 0; kh < 3; ++kh) {
        int yy = y + kh - 1;
#pragma unroll
        for (int kw = 0; kw < 3; ++kw) {
            int xx = x + kw - 1;
            float v = 0.0f;
            if (yy >= 0 && yy < H && xx >= 0 && xx < W) v = fb[yy * W + xx];
            sp[t * 9 + kh * 3 + kw] = v;
        }
    }
    __syncthreads();

    const float4* w4 = (const float4*)(weight + t * DPAT);
    const float4* s4 = (const float4*)sp;
    float acc = __ldg(&bias[t]);
#pragma unroll 8
    for (int d = 0; d < DPAT / 4; ++d) {
        float4 wv = __ldg(&w4[d]);
        float4 sv = s4[d];
        acc = fmaf(sv.x, wv.x, acc);
        acc = fmaf(sv.y, wv.y, acc);
        acc = fmaf(sv.z, wv.z, acc);
        acc = fmaf(sv.w, wv.w, acc);
    }
    g_rep[(n * MEM + b) * COUT + t] = acc;
}

// ---------------------------------------------------------------------------
// Kernel 3: broadcast representative rows to NCHW output, 4x the parallelism:
// thread = (pixel, 16-cout quarter). 4 independent float4 rep loads (L2-hot),
// 16 stores where each warp-STG.32 covers one full 128B line (consecutive
// pixels). Also re-zeros g_first for the next graph replay.
// ---------------------------------------------------------------------------
__global__ void k_scatter(float* __restrict__ out) {
    int tid = threadIdx.x;
    int gid = blockIdx.x * blockDim.x + tid;
    if (gid < N_IMG * MEM) g_first[gid] = 0;   // self-restore for next replay

    int q   = blockIdx.x & 3;                  // cout quarter (16 channels)
    int pix = (blockIdx.x >> 2) * 256 + tid;   // 0 .. N_IMG*HW-1
    int n   = pix / HW;
    int p   = pix - n * HW;
    int bin = g_bins[pix];

    const float4* r4 = (const float4*)(g_rep + (n * MEM + bin) * COUT + q * 16);
    float4 v0 = __ldg(&r4[0]);
    float4 v1 = __ldg(&r4[1]);
    float4 v2 = __ldg(&r4[2]);
    float4 v3 = __ldg(&r4[3]);

    float* ob = out + (n * COUT + q * 16) * HW + p;
    ob[0 * HW]  = v0.x;  ob[1 * HW]  = v0.y;  ob[2 * HW]  = v0.z;  ob[3 * HW]  = v0.w;
    ob[4 * HW]  = v1.x;  ob[5 * HW]  = v1.y;  ob[6 * HW]  = v1.z;  ob[7 * HW]  = v1.w;
    ob[8 * HW]  = v2.x;  ob[9 * HW]  = v2.y;  ob[10 * HW] = v2.z;  ob[11 * HW] = v2.w;
    ob[12 * HW] = v3.x;  ob[13 * HW] = v3.y;  ob[14 * HW] = v3.z;  ob[15 * HW] = v3.w;
}

// ---------------------------------------------------------------------------
extern "C" void kernel_launch(void* const* d_in, const int* in_sizes, int n_in,
                              void* d_out, int out_size) {
    const float* fmap   = (const float*)d_in[0];   // [8,64,112,112]
    const float* weight = (const float*)d_in[1];   // [64,576]
    const float* bias   = (const float*)d_in[2];   // [64]
    float* out = (float*)d_out;                    // [8,64,112,112]
    (void)in_sizes; (void)n_in; (void)out_size;

    k_fused<<<N_IMG * TPI * TPI, 256>>>(fmap);     // 392 blocks
    k_rep<<<N_IMG * MEM, COUT>>>(fmap, weight, bias);
    k_scatter<<<(N_IMG * HW / 256) * 4, 256>>>(out);  // 1568 blocks
}